// round 12
// baseline (speedup 1.0000x reference)
#include <cuda_runtime.h>
#include <cstdint>

// SpikeFP32GELUExact: [B,S,D,32] float 0/1 pulses (MSB-first bits of fp32)
//  -> decode fp32 -> fp64 tanh-GELU (reference formula, ~2ulp-exact) -> fp32 RN
//  -> re-encode as 32 float 0/1 pulses.
//
// FP64-pipe-bound (R6 evidence): custom branch-free exp + Newton division cut
// FP64 ops ~47 -> ~33 per element. Memory path: warp-cooperative single-line
// LDG.32+ballot decode / STG.128+shfl encode (from R6, L1 already fixed).

// exp(y) for |y| <= ~700, accurate to ~3 ulp. Branch-free.
__device__ __forceinline__ double fast_exp(double y)
{
    const double LOG2E  = 1.4426950408889634074;
    const double LN2_HI = 6.93147180369123816490e-01;  // high bits exact
    const double LN2_LO = 1.90821492927058770002e-10;

    int k = __double2int_rn(y * LOG2E);
    k = max(-1021, min(1021, k));            // safety clamp (data never hits)
    double kd = (double)k;
    double r = __fma_rn(kd, -LN2_HI, y);
    r = __fma_rn(kd, -LN2_LO, r);

    // e^r, |r| <= 0.3466, degree-12 Taylor (remainder < 2^-51 rel)
    double p =              2.0876756987868100e-09;   // 1/12!
    p = __fma_rn(p, r,      2.5052108385441720e-08);  // 1/11!
    p = __fma_rn(p, r,      2.7557319223985893e-07);  // 1/10!
    p = __fma_rn(p, r,      2.7557319223985888e-06);  // 1/9!
    p = __fma_rn(p, r,      2.4801587301587302e-05);  // 1/8!
    p = __fma_rn(p, r,      1.9841269841269841e-04);  // 1/7!
    p = __fma_rn(p, r,      1.3888888888888889e-03);  // 1/6!
    p = __fma_rn(p, r,      8.3333333333333332e-03);  // 1/5!
    p = __fma_rn(p, r,      4.1666666666666664e-02);  // 1/4!
    p = __fma_rn(p, r,      1.6666666666666666e-01);  // 1/3!
    p = __fma_rn(p, r,      0.5);
    p = __fma_rn(p, r,      1.0);
    p = __fma_rn(p, r,      1.0);

    double sc = __longlong_as_double(((long long)(1023 + k)) << 52);  // 2^k
    return p * sc;
}

// n/d to ~1 ulp via fp32 rcp seed + 2 Newton iters + residual correction.
// Valid for d in [1, 2^60] (here d = e2z + 1 >= 1, finite).
__device__ __forceinline__ double fast_div(double n, double d)
{
    float df = (float)d;
    float rf;
    asm("rcp.approx.f32 %0, %1;" : "=f"(rf) : "f"(df));
    double y = (double)rf;
    y = __fma_rn(__fma_rn(-d, y, 1.0), y, y);
    y = __fma_rn(__fma_rn(-d, y, 1.0), y, y);
    double q = n * y;
    q = __fma_rn(__fma_rn(-d, q, n), y, q);
    return q;
}

__global__ void __launch_bounds__(256)
gelu_bits_kernel(const float* __restrict__ in, float4* __restrict__ out, int n_tiles)
{
    int gwarp = (blockIdx.x * blockDim.x + threadIdx.x) >> 5;
    int lane  = threadIdx.x & 31;
    if (gwarp >= n_tiles) return;

    const float* p = in + (size_t)gwarp * 1024;   // 32 elements * 32 floats

    // ---- decode: element e's 32-bit word via warp ballot ----
    unsigned u = 0;
#pragma unroll
    for (int e = 0; e < 32; e++) {
        float v = p[e * 32 + lane];                       // coalesced, 1 line
        unsigned b = __ballot_sync(0xffffffffu, v != 0.0f);
        if (lane == e) u = b;
    }
    u = __brev(u);

    // ---- compute: lane l owns element l; fp64 tanh-GELU, reference order ----
    float xf = __uint_as_float(u);
    double x = (double)xf;
    double x_sq = x * x;
    double x_cubed = x_sq * x;
    double inner = x + 0.044715 * x_cubed;
    double z = 0.7978845608028654 * inner;
    double e2z = fast_exp(2.0 * z);
    double tanh_z = fast_div(e2z - 1.0, e2z + 1.0);
    double res64 = 0.5 * (x * (1.0 + tanh_z));
    float rf = (float)res64;                              // RN downcast

    unsigned rb = __brev(__float_as_uint(rf));

    // ---- encode: 8 coalesced STG.128 per warp-tile ----
    float4* q = out + (size_t)gwarp * 256;                // 256 float4 per tile
#pragma unroll
    for (int j = 0; j < 8; j++) {
        int e = j * 4 + (lane >> 3);
        unsigned rr = __shfl_sync(0xffffffffu, rb, e);
        int qd = (lane & 7) * 4;
        float4 o;
        o.x = ((rr >> (qd + 0)) & 1u) ? 1.0f : 0.0f;
        o.y = ((rr >> (qd + 1)) & 1u) ? 1.0f : 0.0f;
        o.z = ((rr >> (qd + 2)) & 1u) ? 1.0f : 0.0f;
        o.w = ((rr >> (qd + 3)) & 1u) ? 1.0f : 0.0f;
        q[j * 32 + lane] = o;
    }
}

extern "C" void kernel_launch(void* const* d_in, const int* in_sizes, int n_in,
                              void* d_out, int out_size)
{
    (void)n_in; (void)out_size;
    const float* in = (const float*)d_in[0];
    float4* out = (float4*)d_out;
    int n_elem  = in_sizes[0] / 32;            // B*S*D = 4,194,304
    int n_tiles = (n_elem + 31) / 32;          // 32 elements per warp

    int threads = 256;                          // 8 warps -> 8 tiles per block
    int warps_per_block = threads / 32;
    int blocks = (n_tiles + warps_per_block - 1) / warps_per_block;
    gelu_bits_kernel<<<blocks, threads>>>(in, out, n_tiles);
}